// round 16
// baseline (speedup 1.0000x reference)
#include <cuda_runtime.h>
#include <cstdint>

// Embedding gather: out[token, :] = embedding[input_ids[token], :]
// input_ids: [4096] i32, embedding: [32000,1024] f32, out: [4096,1024] f32
//
// Persistent-grid variant: 296 CTAs x 512 threads = 2 CTAs/SM, 2048
// threads/SM (full thread occupancy), each CTA loops over strided tokens.
//  - only 296 CTA placements (vs 1024+) -> shorter GigaThread ramp
//  - 512 threads cover 2 rows per iteration (256 x float4 each)
//  - unroll-2 loop: iteration i+1's independent id/row loads overlap
//    iteration i's stores via the scoreboard (loop-carried MLP instead of
//    front-batched MLP, avoiding the L1tex front-batch queue penalty)
//  - stride assignment: token = iter*(296*2) + blockIdx.x*2 + (tid>>8),
//    balanced to +-1 iteration across CTAs, guard handles the tail.

static constexpr int ROW_F4   = 256;   // float4 per 4 KB row
static constexpr int NUM_CTAS = 296;   // 2 per SM on 148 SMs
static constexpr int TPB      = 512;
static constexpr int TOK_PER_ITER = NUM_CTAS * 2;   // 592 tokens per sweep

__global__ void __launch_bounds__(TPB)
embed_gather_persist(const int* __restrict__ ids,
                     const float4* __restrict__ emb,
                     float4* __restrict__ out,
                     int n_tokens)
{
    const int sub   = threadIdx.x & 255;        // float4 index within row
    const int which = threadIdx.x >> 8;         // 0 or 1: which of 2 tokens
    const int tok0  = blockIdx.x * 2 + which;   // first token for this half

#pragma unroll 2
    for (int t = tok0; t < n_tokens; t += TOK_PER_ITER) {
        int id = ids[t];                                   // uniform per half-CTA
        float4 v = emb[(size_t)id * ROW_F4 + sub];         // coalesced row read
        out[(size_t)t * ROW_F4 + sub] = v;                 // coalesced row write
    }
}

extern "C" void kernel_launch(void* const* d_in, const int* in_sizes, int n_in,
                              void* d_out, int out_size)
{
    const int*    ids = (const int*)d_in[0];
    const float4* emb = (const float4*)d_in[1];
    float4*       out = (float4*)d_out;

    int n_tokens = in_sizes[0];   // 4096
    embed_gather_persist<<<NUM_CTAS, TPB>>>(ids, emb, out, n_tokens);
}

// round 17
// speedup vs baseline: 1.0258x; 1.0258x over previous
#include <cuda_runtime.h>
#include <cstdint>

// Embedding gather: out[token, :] = embedding[input_ids[token], :]
// input_ids: [4096] i32, embedding: [32000,1024] f32, out: [4096,1024] f32
//
// Persistent grid (296 CTAs x 512 threads, 2/SM, full thread occupancy) with
// the loop-carried id->row dependency chain BROKEN: all ~7 token ids per
// thread are prefetched in one independent burst at kernel start, so the
// row-copy loop has no serial id dependency — row load i+1 issues while
// store i drains. Only one id-latency exposure for the whole kernel.
// (R16 showed the tight persistent loop re-pays the ~1200-cyc chain every
// iteration; this isolates and removes exactly that term.)

static constexpr int ROW_F4       = 256;           // float4 per 4 KB row
static constexpr int NUM_CTAS     = 296;           // 2 per SM
static constexpr int TPB          = 512;
static constexpr int TOK_PER_ITER = NUM_CTAS * 2;  // 592
static constexpr int MAX_ITERS    = 7;             // ceil(4096 / 592)

__global__ void __launch_bounds__(TPB)
embed_gather_prefetch(const int* __restrict__ ids,
                      const float4* __restrict__ emb,
                      float4* __restrict__ out,
                      int n_tokens)
{
    const int sub   = threadIdx.x & 255;        // float4 index within row
    const int which = threadIdx.x >> 8;         // 0 or 1
    const int tok0  = blockIdx.x * 2 + which;

    // --- Prefetch ALL ids in one independent burst (breaks the chain) ---
    int id[MAX_ITERS];
#pragma unroll
    for (int i = 0; i < MAX_ITERS; i++) {
        int t = tok0 + i * TOK_PER_ITER;
        id[i] = (t < n_tokens) ? ids[t] : 0;    // predicated, still independent
    }

    // --- Row copy loop: no id dependency inside; iterations overlap ---
#pragma unroll
    for (int i = 0; i < MAX_ITERS; i++) {
        int t = tok0 + i * TOK_PER_ITER;
        if (t < n_tokens) {
            float4 v = emb[(size_t)id[i] * ROW_F4 + sub];
            out[(size_t)t * ROW_F4 + sub] = v;
        }
    }
}

extern "C" void kernel_launch(void* const* d_in, const int* in_sizes, int n_in,
                              void* d_out, int out_size)
{
    const int*    ids = (const int*)d_in[0];
    const float4* emb = (const float4*)d_in[1];
    float4*       out = (float4*)d_out;

    int n_tokens = in_sizes[0];   // 4096
    embed_gather_prefetch<<<NUM_CTAS, TPB>>>(ids, emb, out, n_tokens);
}